// round 11
// baseline (speedup 1.0000x reference)
#include <cuda_runtime.h>

#define B_   8
#define N_   16384
#define NC_  64
#define C_   256
#define TP_  128
#define SP_STRIDE 20     // P stage row stride; 16B-idx = 5*lane + c -> conflict-free
#define SE_STRIDE 68     // E row stride; 16B-idx = 17*lane + c -> conflict-free

// Scratch (device globals — no allocation allowed)
__device__ float g_M[B_ * C_ * NC_];  // [b][c][k]
__device__ float g_t[B_ * NC_];       // [b][k]

typedef unsigned long long ull;

__device__ __forceinline__ ull pack2(float x, float y) {
    ull r; asm("mov.b64 %0, {%1, %2};" : "=l"(r) : "f"(x), "f"(y)); return r;
}
__device__ __forceinline__ void unpack2(ull v, float &x, float &y) {
    asm("mov.b64 {%0, %1}, %2;" : "=f"(x), "=f"(y) : "l"(v));
}
__device__ __forceinline__ void fma2(ull &acc, ull a, ull b) {
    asm("fma.rn.f32x2 %0, %1, %2, %3;" : "=l"(acc) : "l"(a), "l"(b), "l"(acc));
}
__device__ __forceinline__ float warp_sum(float s) {
#pragma unroll
    for (int off = 16; off; off >>= 1) s += __shfl_xor_sync(0xffffffffu, s, off);
    return s;
}

// ---------------------------------------------------------------------------
// Prep kernel (unchanged). grid 128 = (b<<4 | kt), block 256.
// ---------------------------------------------------------------------------
__global__ void prep_kernel(const float* __restrict__ cf, const float* __restrict__ Wp,
                            const float* __restrict__ Wc, const float* __restrict__ bp,
                            const float* __restrict__ bc) {
    __shared__ __align__(16) float sCt[C_ * 4];
    __shared__ __align__(16) float sCPt[C_ * 4];
    __shared__ __align__(16) float sTile[8448];
    __shared__ float sPart[8][4];

    int b  = blockIdx.x >> 4;
    int kt = blockIdx.x & 15;
    int tid = threadIdx.x, w = tid >> 5, l = tid & 31;

#pragma unroll
    for (int i = 0; i < 4; i++)
        sCt[tid * 4 + i] = cf[(size_t)(b * NC_ + kt * 4 + i) * C_ + tid];
    __syncthreads();

    int d = tid;
    float acc[4];
    {
        float bcv = bc[d];
#pragma unroll
        for (int j = 0; j < 4; j++) acc[j] = bcv;
    }
    const float4* Wc4 = (const float4*)Wc;
    for (int e0 = 0; e0 < C_; e0 += 32) {
#pragma unroll
        for (int i = 0; i < 8; i++) {
            int q = tid + 256 * i;
            int ee = q >> 6, jf = q & 63;
            ((float4*)sTile)[ee * 66 + jf] = Wc4[(size_t)(e0 + ee) * 64 + jf];
        }
        __syncthreads();
#pragma unroll 4
        for (int ee = 0; ee < 32; ee++) {
            float wv = sTile[ee * 264 + d];
            float4 c0 = *(const float4*)(sCt + (e0 + ee) * 4);
            acc[0] += wv*c0.x; acc[1] += wv*c0.y; acc[2] += wv*c0.z; acc[3] += wv*c0.w;
        }
        __syncthreads();
    }
    {
        float m = bp[d];
#pragma unroll
        for (int j = 0; j < 4; j++) {
            float s = warp_sum(acc[j] * m);
            if (l == 0) sPart[w][j] = s;
        }
    }
    *(float4*)(sCPt + d * 4) = make_float4(acc[0], acc[1], acc[2], acc[3]);
    __syncthreads();
    if (tid < 4) {
        float s = 0.f;
#pragma unroll
        for (int ww = 0; ww < 8; ww++) s += sPart[ww][tid];
        g_t[b * NC_ + kt * 4 + tid] = s;
    }

    int c = tid;
    float a2[4] = {0.f, 0.f, 0.f, 0.f};
    const float4* Wp4 = (const float4*)Wp;
    for (int d0 = 0; d0 < C_; d0 += 32) {
        __syncthreads();
#pragma unroll
        for (int i = 0; i < 8; i++) {
            int q = tid + 256 * i;
            int cc = q >> 3, jf = q & 7;
            float4 v = Wp4[(size_t)cc * 64 + d0 / 4 + jf];
            float* dst = sTile + cc * 33 + jf * 4;
            dst[0] = v.x; dst[1] = v.y; dst[2] = v.z; dst[3] = v.w;
        }
        __syncthreads();
#pragma unroll 4
        for (int dd = 0; dd < 32; dd++) {
            float wv = sTile[c * 33 + dd];
            float4 q0 = *(const float4*)(sCPt + (d0 + dd) * 4);
            a2[0] += wv*q0.x; a2[1] += wv*q0.y; a2[2] += wv*q0.z; a2[3] += wv*q0.w;
        }
    }
#pragma unroll
    for (int j = 0; j < 4; j++)
        g_M[(size_t)(b * C_ + c) * NC_ + kt * 4 + j] = a2[j];
}

// ---------------------------------------------------------------------------
// Main kernel. Block 256 thr (8 warps), 128 points, 3 blocks/SM.
// WARP-UNIFORM operand mapping: warp wid owns k/ch octet {4w..4w+3}U{32+4w..};
// lanes = 32 points; each lane handles 4 points (lane + 32p).
// M / Ctr smem reads are all-lanes-same-address (broadcast, 1 wavefront).
// Softmax: per-lane over own 8 k, then cross-warp reduce via smem.
// dyn smem = 18944 floats (75.8 KB):
//   phase1: sM [0,16384) = M[c][64];  sP/sRed [16384, 18944)
//   phase2 overlay: sE [0, 128*68=8704), sCtr [8704, 12800)
// ---------------------------------------------------------------------------
__global__ __launch_bounds__(256, 3)
void attn_main_kernel(const float* __restrict__ pf, const float* __restrict__ cf,
                      float* __restrict__ out) {
    extern __shared__ __align__(16) float sm[];
    float* sM    = sm;
    float* sP    = sm + 16384;
    float* sRed1 = sm + 16384;          // 8 x 128 (overlays sP after phase 1)
    float* sRed2 = sm + 16384 + 1024;   // 8 x 128
    float* sE    = sm;
    float* sCtr  = sm + 8704;
    __shared__ __align__(16) float st[NC_];

    int b    = blockIdx.x >> 7;
    int tile = blockIdx.x & 127;
    int tid  = threadIdx.x;
    int wid  = tid >> 5;    // k / ch octet
    int lane = tid & 31;    // point group

    {
        const float4* Ms = (const float4*)(g_M + (size_t)b * C_ * NC_);
        float4* s4 = (float4*)sM;
#pragma unroll
        for (int i = 0; i < 16; i++) s4[tid + 256 * i] = Ms[tid + 256 * i];
        if (tid < NC_) st[tid] = g_t[b * NC_ + tid];
    }
    __syncthreads();

    size_t ptbase = (size_t)b * N_ + (size_t)tile * TP_;
    const float* pbase = pf + ptbase * C_;
    float* obase = out + ptbase * C_;

    // ---- phase 1: scores for k-octet of warp wid, 4 points per lane ----
    ull acc[4][4];
    {
        const ull* t2 = (const ull*)st;
        ull i0 = t2[2*wid], i1 = t2[2*wid+1], i2 = t2[16+2*wid], i3 = t2[17+2*wid];
#pragma unroll
        for (int p = 0; p < 4; p++) {
            acc[p][0] = i0; acc[p][1] = i1; acc[p][2] = i2; acc[p][3] = i3;
        }
    }

#pragma unroll 1
    for (int ch = 0; ch < 16; ch++) {       // 16-channel chunks
        if (ch) __syncthreads();
#pragma unroll
        for (int i = 0; i < 2; i++) {
            int q  = tid + 256 * i;
            int pt = q >> 2, jf = q & 3;
            *(float4*)(sP + pt * SP_STRIDE + jf * 4) =
                *(const float4*)(pbase + (size_t)pt * C_ + ch * 16 + jf * 4);
        }
        __syncthreads();

#pragma unroll
        for (int c4 = 0; c4 < 4; c4++) {
            float4 pv[4];
#pragma unroll
            for (int p = 0; p < 4; p++)
                pv[p] = *(const float4*)(sP + (lane + 32 * p) * SP_STRIDE + c4 * 4);
#pragma unroll
            for (int j = 0; j < 4; j++) {
                const float* mrow = sM + (size_t)(ch * 16 + c4 * 4 + j) * NC_;
                ulonglong2 m0 = *(const ulonglong2*)(mrow + wid * 4);        // uniform
                ulonglong2 m1 = *(const ulonglong2*)(mrow + 32 + wid * 4);   // uniform
                float pj[4] = {pv[0].x, pv[1].x, pv[2].x, pv[3].x};
                if (j == 1) { pj[0]=pv[0].y; pj[1]=pv[1].y; pj[2]=pv[2].y; pj[3]=pv[3].y; }
                else if (j == 2) { pj[0]=pv[0].z; pj[1]=pv[1].z; pj[2]=pv[2].z; pj[3]=pv[3].z; }
                else if (j == 3) { pj[0]=pv[0].w; pj[1]=pv[1].w; pj[2]=pv[2].w; pj[3]=pv[3].w; }
#pragma unroll
                for (int p = 0; p < 4; p++) {
                    ull pp = pack2(pj[p], pj[p]);
                    fma2(acc[p][0], m0.x, pp);
                    fma2(acc[p][1], m0.y, pp);
                    fma2(acc[p][2], m1.x, pp);
                    fma2(acc[p][3], m1.y, pp);
                }
            }
        }
    }
    __syncthreads();   // phase-1 sP reads done; sRed overlays sP

    // ---- softmax: cross-warp reduce (each warp holds 8 of 64 k per point) ----
    float ex[4][8];
    float lsum[4];
#pragma unroll
    for (int p = 0; p < 4; p++) {
        float x0,x1,x2,x3,x4,x5,x6,x7;
        unpack2(acc[p][0], x0, x1); unpack2(acc[p][1], x2, x3);
        unpack2(acc[p][2], x4, x5); unpack2(acc[p][3], x6, x7);
        float mx = fmaxf(fmaxf(fmaxf(x0,x1),fmaxf(x2,x3)), fmaxf(fmaxf(x4,x5),fmaxf(x6,x7)));
        sRed1[wid * 128 + lane + 32 * p] = mx;
        ex[p][0]=x0; ex[p][1]=x1; ex[p][2]=x2; ex[p][3]=x3;
        ex[p][4]=x4; ex[p][5]=x5; ex[p][6]=x6; ex[p][7]=x7;
    }
    __syncthreads();
#pragma unroll
    for (int p = 0; p < 4; p++) {
        int pt = lane + 32 * p;
        float g = sRed1[pt];
#pragma unroll
        for (int w = 1; w < 8; w++) g = fmaxf(g, sRed1[w * 128 + pt]);
        float s = 0.f;
#pragma unroll
        for (int q = 0; q < 8; q++) { ex[p][q] = __expf(ex[p][q] - g); s += ex[p][q]; }
        lsum[p] = s;
        sRed2[wid * 128 + pt] = s;
    }
    __syncthreads();
#pragma unroll
    for (int p = 0; p < 4; p++) {
        int pt = lane + 32 * p;
        float s = sRed2[pt];
#pragma unroll
        for (int w = 1; w < 8; w++) s += sRed2[w * 128 + pt];
        float inv = 1.0f / s;
        (void)lsum;
#pragma unroll
        for (int q = 0; q < 8; q++) ex[p][q] *= inv;
    }
    __syncthreads();   // sRed reads done; sE overlays sM (sM reads long done)

    // ---- stage E: sE[pt][64]; warp wid writes its k-octet slice ----
#pragma unroll
    for (int p = 0; p < 4; p++) {
        float* er = sE + (lane + 32 * p) * SE_STRIDE;
        ulonglong2 e0;
        e0.x = pack2(ex[p][0], ex[p][1]); e0.y = pack2(ex[p][2], ex[p][3]);
        ulonglong2 e1;
        e1.x = pack2(ex[p][4], ex[p][5]); e1.y = pack2(ex[p][6], ex[p][7]);
        *(ulonglong2*)(er + wid * 4)      = e0;
        *(ulonglong2*)(er + 32 + wid * 4) = e1;
    }

    // ---- phase 2: warp = ch-octet; Ctr uniform reads; E per-lane ----
#pragma unroll 1
    for (int cc2 = 0; cc2 < 4; cc2++) {
        if (cc2) __syncthreads();
#pragma unroll
        for (int i = 0; i < 4; i++) {
            int q = tid + 256 * i;
            int k = q >> 4, jf = q & 15;
            *(float4*)(sCtr + k * 64 + jf * 4) =
                *(const float4*)(cf + (size_t)(b * NC_ + k) * C_ + cc2 * 64 + jf * 4);
        }
        __syncthreads();   // sCtr ready; sE visible on first pass

        ull a2[4][4];
#pragma unroll
        for (int p = 0; p < 4; p++) { a2[p][0]=0; a2[p][1]=0; a2[p][2]=0; a2[p][3]=0; }

#pragma unroll 2
        for (int k4 = 0; k4 < 16; k4++) {
            float4 ev[4];
#pragma unroll
            for (int p = 0; p < 4; p++)
                ev[p] = *(const float4*)(sE + (lane + 32 * p) * SE_STRIDE + k4 * 4);
#pragma unroll
            for (int j = 0; j < 4; j++) {
                const float* crow = sCtr + (size_t)(k4 * 4 + j) * 64;
                ulonglong2 c0 = *(const ulonglong2*)(crow + wid * 4);        // uniform
                ulonglong2 c1 = *(const ulonglong2*)(crow + 32 + wid * 4);   // uniform
                float ej[4] = {ev[0].x, ev[1].x, ev[2].x, ev[3].x};
                if (j == 1) { ej[0]=ev[0].y; ej[1]=ev[1].y; ej[2]=ev[2].y; ej[3]=ev[3].y; }
                else if (j == 2) { ej[0]=ev[0].z; ej[1]=ev[1].z; ej[2]=ev[2].z; ej[3]=ev[3].z; }
                else if (j == 3) { ej[0]=ev[0].w; ej[1]=ev[1].w; ej[2]=ev[2].w; ej[3]=ev[3].w; }
#pragma unroll
                for (int p = 0; p < 4; p++) {
                    ull pp = pack2(ej[p], ej[p]);
                    fma2(a2[p][0], c0.x, pp);
                    fma2(a2[p][1], c0.y, pp);
                    fma2(a2[p][2], c1.x, pp);
                    fma2(a2[p][3], c1.y, pp);
                }
            }
        }

        // epilogue: residual + store (16B per lane; 8 warps tile each 128B line)
#pragma unroll
        for (int p = 0; p < 4; p++) {
            size_t roff = (size_t)(lane + 32 * p) * C_ + cc2 * 64 + wid * 4;
            float4 v0 = *(const float4*)(pbase + roff);
            float4 v1 = *(const float4*)(pbase + roff + 32);
            float a, bb;
            unpack2(a2[p][0], a, bb); v0.x += a; v0.y += bb;
            unpack2(a2[p][1], a, bb); v0.z += a; v0.w += bb;
            unpack2(a2[p][2], a, bb); v1.x += a; v1.y += bb;
            unpack2(a2[p][3], a, bb); v1.z += a; v1.w += bb;
            *(float4*)(obase + roff)      = v0;
            *(float4*)(obase + roff + 32) = v1;
        }
    }
}

// ---------------------------------------------------------------------------
extern "C" void kernel_launch(void* const* d_in, const int* in_sizes, int n_in,
                              void* d_out, int out_size) {
    const float* pf = (const float*)d_in[0];   // point_features   (B,N,C)
    const float* cf = (const float*)d_in[1];   // centroid_features(B,NC,C)
    const float* Wp = (const float*)d_in[2];   // (C,C)
    const float* bp = (const float*)d_in[3];   // (C,)
    const float* Wc = (const float*)d_in[4];   // (C,C)
    const float* bc = (const float*)d_in[5];   // (C,)
    float* out = (float*)d_out;

    const int smem_bytes = 18944 * sizeof(float);   // 75.8 KB -> 3 blocks/SM

    static bool attr_set = false;
    if (!attr_set) {
        cudaFuncSetAttribute(attn_main_kernel,
                             cudaFuncAttributeMaxDynamicSharedMemorySize,
                             smem_bytes);
        attr_set = true;
    }

    prep_kernel<<<B_ * 16, 256>>>(cf, Wp, Wc, bp, bc);
    attn_main_kernel<<<B_ * (N_ / TP_), 256, smem_bytes>>>(pf, cf, out);
}

// round 12
// speedup vs baseline: 1.2995x; 1.2995x over previous
#include <cuda_runtime.h>

#define B_   8
#define N_   16384
#define NC_  64
#define C_   256
#define TP_  128
#define SP_STRIDE 20     // P stage row stride; conflict-free strided reads
#define SE_STRIDE 68     // E row stride

// Scratch (device globals — no allocation allowed)
__device__ float g_M[B_ * C_ * NC_];  // [b][c][k]
__device__ float g_t[B_ * NC_];       // [b][k]

typedef unsigned long long ull;

__device__ __forceinline__ ull pack2(float x, float y) {
    ull r; asm("mov.b64 %0, {%1, %2};" : "=l"(r) : "f"(x), "f"(y)); return r;
}
__device__ __forceinline__ void unpack2(ull v, float &x, float &y) {
    asm("mov.b64 {%0, %1}, %2;" : "=f"(x), "=f"(y) : "l"(v));
}
__device__ __forceinline__ void fma2(ull &acc, ull a, ull b) {
    asm("fma.rn.f32x2 %0, %1, %2, %3;" : "=l"(acc) : "l"(a), "l"(b), "l"(acc));
}
__device__ __forceinline__ float warp_sum(float s) {
#pragma unroll
    for (int off = 16; off; off >>= 1) s += __shfl_xor_sync(0xffffffffu, s, off);
    return s;
}

// ---------------------------------------------------------------------------
// Prep kernel (unchanged). grid 128 = (b<<4 | kt), block 256.
// ---------------------------------------------------------------------------
__global__ void prep_kernel(const float* __restrict__ cf, const float* __restrict__ Wp,
                            const float* __restrict__ Wc, const float* __restrict__ bp,
                            const float* __restrict__ bc) {
    __shared__ __align__(16) float sCt[C_ * 4];
    __shared__ __align__(16) float sCPt[C_ * 4];
    __shared__ __align__(16) float sTile[8448];
    __shared__ float sPart[8][4];

    int b  = blockIdx.x >> 4;
    int kt = blockIdx.x & 15;
    int tid = threadIdx.x, w = tid >> 5, l = tid & 31;

#pragma unroll
    for (int i = 0; i < 4; i++)
        sCt[tid * 4 + i] = cf[(size_t)(b * NC_ + kt * 4 + i) * C_ + tid];
    __syncthreads();

    int d = tid;
    float acc[4];
    {
        float bcv = bc[d];
#pragma unroll
        for (int j = 0; j < 4; j++) acc[j] = bcv;
    }
    const float4* Wc4 = (const float4*)Wc;
    for (int e0 = 0; e0 < C_; e0 += 32) {
#pragma unroll
        for (int i = 0; i < 8; i++) {
            int q = tid + 256 * i;
            int ee = q >> 6, jf = q & 63;
            ((float4*)sTile)[ee * 66 + jf] = Wc4[(size_t)(e0 + ee) * 64 + jf];
        }
        __syncthreads();
#pragma unroll 4
        for (int ee = 0; ee < 32; ee++) {
            float wv = sTile[ee * 264 + d];
            float4 c0 = *(const float4*)(sCt + (e0 + ee) * 4);
            acc[0] += wv*c0.x; acc[1] += wv*c0.y; acc[2] += wv*c0.z; acc[3] += wv*c0.w;
        }
        __syncthreads();
    }
    {
        float m = bp[d];
#pragma unroll
        for (int j = 0; j < 4; j++) {
            float s = warp_sum(acc[j] * m);
            if (l == 0) sPart[w][j] = s;
        }
    }
    *(float4*)(sCPt + d * 4) = make_float4(acc[0], acc[1], acc[2], acc[3]);
    __syncthreads();
    if (tid < 4) {
        float s = 0.f;
#pragma unroll
        for (int ww = 0; ww < 8; ww++) s += sPart[ww][tid];
        g_t[b * NC_ + kt * 4 + tid] = s;
    }

    int c = tid;
    float a2[4] = {0.f, 0.f, 0.f, 0.f};
    const float4* Wp4 = (const float4*)Wp;
    for (int d0 = 0; d0 < C_; d0 += 32) {
        __syncthreads();
#pragma unroll
        for (int i = 0; i < 8; i++) {
            int q = tid + 256 * i;
            int cc = q >> 3, jf = q & 7;
            float4 v = Wp4[(size_t)cc * 64 + d0 / 4 + jf];
            float* dst = sTile + cc * 33 + jf * 4;
            dst[0] = v.x; dst[1] = v.y; dst[2] = v.z; dst[3] = v.w;
        }
        __syncthreads();
#pragma unroll 4
        for (int dd = 0; dd < 32; dd++) {
            float wv = sTile[c * 33 + dd];
            float4 q0 = *(const float4*)(sCPt + (d0 + dd) * 4);
            a2[0] += wv*q0.x; a2[1] += wv*q0.y; a2[2] += wv*q0.z; a2[3] += wv*q0.w;
        }
    }
#pragma unroll
    for (int j = 0; j < 4; j++)
        g_M[(size_t)(b * C_ + c) * NC_ + kt * 4 + j] = a2[j];
}

// ---------------------------------------------------------------------------
// Main kernel. Block 256 thr (8 warps), 128 points, 3 blocks/SM.
// Phase 1 (unchanged r11): warp = k-octet, lane = points. M reads uniform
// (broadcast, 1 wf); P staged coalesced.
// Phase 2 (REMAPPED): warp = 16 consecutive points, lane = 4 consecutive ch
// over a 128-ch half. Ctr LDS conflict-free, E uniform, epilogue COALESCED.
// dyn smem = 18944 floats (75.8 KB):
//   phase1: sM [0,16384); sP [16384,18944)
//   softmax: sRed1 [16896,17920), sRed2 [17920,18944)  (overlay sP tail)
//   phase2: sE [0,8704), sCtr [8704,16896)             (overlay sM)
// ---------------------------------------------------------------------------
__global__ __launch_bounds__(256, 3)
void attn_main_kernel(const float* __restrict__ pf, const float* __restrict__ cf,
                      float* __restrict__ out) {
    extern __shared__ __align__(16) float sm[];
    float* sM    = sm;
    float* sP    = sm + 16384;
    float* sRed1 = sm + 16896;
    float* sRed2 = sm + 17920;
    float* sE    = sm;
    float* sCtr  = sm + 8704;
    __shared__ __align__(16) float st[NC_];

    int b    = blockIdx.x >> 7;
    int tile = blockIdx.x & 127;
    int tid  = threadIdx.x;
    int wid  = tid >> 5;
    int lane = tid & 31;

    {
        const float4* Ms = (const float4*)(g_M + (size_t)b * C_ * NC_);
        float4* s4 = (float4*)sM;
#pragma unroll
        for (int i = 0; i < 16; i++) s4[tid + 256 * i] = Ms[tid + 256 * i];
        if (tid < NC_) st[tid] = g_t[b * NC_ + tid];
    }
    __syncthreads();

    size_t ptbase = (size_t)b * N_ + (size_t)tile * TP_;
    const float* pbase = pf + ptbase * C_;
    float* obase = out + ptbase * C_;

    // ---- phase 1: scores for k-octet of warp wid, 4 points per lane ----
    ull acc[4][4];
    {
        const ull* t2 = (const ull*)st;
        ull i0 = t2[2*wid], i1 = t2[2*wid+1], i2 = t2[16+2*wid], i3 = t2[17+2*wid];
#pragma unroll
        for (int p = 0; p < 4; p++) {
            acc[p][0] = i0; acc[p][1] = i1; acc[p][2] = i2; acc[p][3] = i3;
        }
    }

#pragma unroll 1
    for (int ch = 0; ch < 16; ch++) {       // 16-channel chunks
        if (ch) __syncthreads();
#pragma unroll
        for (int i = 0; i < 2; i++) {
            int q  = tid + 256 * i;
            int pt = q >> 2, jf = q & 3;
            *(float4*)(sP + pt * SP_STRIDE + jf * 4) =
                *(const float4*)(pbase + (size_t)pt * C_ + ch * 16 + jf * 4);
        }
        __syncthreads();

#pragma unroll
        for (int c4 = 0; c4 < 4; c4++) {
            float4 pv[4];
#pragma unroll
            for (int p = 0; p < 4; p++)
                pv[p] = *(const float4*)(sP + (lane + 32 * p) * SP_STRIDE + c4 * 4);
#pragma unroll
            for (int j = 0; j < 4; j++) {
                const float* mrow = sM + (size_t)(ch * 16 + c4 * 4 + j) * NC_;
                ulonglong2 m0 = *(const ulonglong2*)(mrow + wid * 4);        // uniform
                ulonglong2 m1 = *(const ulonglong2*)(mrow + 32 + wid * 4);   // uniform
                float pj[4] = {pv[0].x, pv[1].x, pv[2].x, pv[3].x};
                if (j == 1) { pj[0]=pv[0].y; pj[1]=pv[1].y; pj[2]=pv[2].y; pj[3]=pv[3].y; }
                else if (j == 2) { pj[0]=pv[0].z; pj[1]=pv[1].z; pj[2]=pv[2].z; pj[3]=pv[3].z; }
                else if (j == 3) { pj[0]=pv[0].w; pj[1]=pv[1].w; pj[2]=pv[2].w; pj[3]=pv[3].w; }
#pragma unroll
                for (int p = 0; p < 4; p++) {
                    ull pp = pack2(pj[p], pj[p]);
                    fma2(acc[p][0], m0.x, pp);
                    fma2(acc[p][1], m0.y, pp);
                    fma2(acc[p][2], m1.x, pp);
                    fma2(acc[p][3], m1.y, pp);
                }
            }
        }
    }
    __syncthreads();   // phase-1 sP reads done; sRed overlays sP tail

    // ---- softmax: cross-warp reduce (each warp holds 8 of 64 k per point) ----
    float ex[4][8];
#pragma unroll
    for (int p = 0; p < 4; p++) {
        float x0,x1,x2,x3,x4,x5,x6,x7;
        unpack2(acc[p][0], x0, x1); unpack2(acc[p][1], x2, x3);
        unpack2(acc[p][2], x4, x5); unpack2(acc[p][3], x6, x7);
        float mx = fmaxf(fmaxf(fmaxf(x0,x1),fmaxf(x2,x3)), fmaxf(fmaxf(x4,x5),fmaxf(x6,x7)));
        sRed1[wid * 128 + lane + 32 * p] = mx;
        ex[p][0]=x0; ex[p][1]=x1; ex[p][2]=x2; ex[p][3]=x3;
        ex[p][4]=x4; ex[p][5]=x5; ex[p][6]=x6; ex[p][7]=x7;
    }
    __syncthreads();
#pragma unroll
    for (int p = 0; p < 4; p++) {
        int pt = lane + 32 * p;
        float g = sRed1[pt];
#pragma unroll
        for (int w = 1; w < 8; w++) g = fmaxf(g, sRed1[w * 128 + pt]);
        float s = 0.f;
#pragma unroll
        for (int q = 0; q < 8; q++) { ex[p][q] = __expf(ex[p][q] - g); s += ex[p][q]; }
        sRed2[wid * 128 + pt] = s;
    }
    __syncthreads();
#pragma unroll
    for (int p = 0; p < 4; p++) {
        int pt = lane + 32 * p;
        float s = sRed2[pt];
#pragma unroll
        for (int w = 1; w < 8; w++) s += sRed2[w * 128 + pt];
        float inv = 1.0f / s;
#pragma unroll
        for (int q = 0; q < 8; q++) ex[p][q] *= inv;
    }
    __syncthreads();   // sRed reads done; sE overlays sM (dead since phase 1)

    // ---- stage E: sE[pt][64]; warp wid writes its k-octet slice ----
#pragma unroll
    for (int p = 0; p < 4; p++) {
        float* er = sE + (lane + 32 * p) * SE_STRIDE;
        ulonglong2 e0;
        e0.x = pack2(ex[p][0], ex[p][1]); e0.y = pack2(ex[p][2], ex[p][3]);
        ulonglong2 e1;
        e1.x = pack2(ex[p][4], ex[p][5]); e1.y = pack2(ex[p][6], ex[p][7]);
        *(ulonglong2*)(er + wid * 4)      = e0;
        *(ulonglong2*)(er + 32 + wid * 4) = e1;
    }

    // ---- phase 2: warp = 16 consecutive points, lane = 4 consecutive ch ----
#pragma unroll 1
    for (int half = 0; half < 2; half++) {
        __syncthreads();   // sCtr region safe; also publishes sE on first pass
        // stage Ctr[64 k][128 ch half], coalesced
#pragma unroll
        for (int i = 0; i < 8; i++) {
            int q = tid + 256 * i;       // 0..2047
            int k = q >> 5, jf = q & 31;
            *(float4*)(sCtr + k * 128 + jf * 4) =
                *(const float4*)(cf + (size_t)(b * NC_ + k) * C_ + half * 128 + jf * 4);
        }
        __syncthreads();

        int pt0w = wid * 16;
#pragma unroll 1
        for (int pg = 0; pg < 4; pg++) {
            int pt0 = pt0w + pg * 4;
            ull a2[4][2];
#pragma unroll
            for (int p = 0; p < 4; p++) { a2[p][0] = 0; a2[p][1] = 0; }

#pragma unroll 2
            for (int k4 = 0; k4 < 16; k4++) {
                ulonglong2 cv[4];
#pragma unroll
                for (int j = 0; j < 4; j++)
                    cv[j] = *(const ulonglong2*)(sCtr + (size_t)(k4 * 4 + j) * 128 + lane * 4);
                float4 ev[4];
#pragma unroll
                for (int p = 0; p < 4; p++)
                    ev[p] = *(const float4*)(sE + (pt0 + p) * SE_STRIDE + k4 * 4);  // uniform
#pragma unroll
                for (int p = 0; p < 4; p++) {
                    ull e;
                    e = pack2(ev[p].x, ev[p].x);
                    fma2(a2[p][0], cv[0].x, e); fma2(a2[p][1], cv[0].y, e);
                    e = pack2(ev[p].y, ev[p].y);
                    fma2(a2[p][0], cv[1].x, e); fma2(a2[p][1], cv[1].y, e);
                    e = pack2(ev[p].z, ev[p].z);
                    fma2(a2[p][0], cv[2].x, e); fma2(a2[p][1], cv[2].y, e);
                    e = pack2(ev[p].w, ev[p].w);
                    fma2(a2[p][0], cv[3].x, e); fma2(a2[p][1], cv[3].y, e);
                }
            }

            // epilogue: residual + COALESCED store (32 lanes x 16B contiguous)
#pragma unroll
            for (int p = 0; p < 4; p++) {
                size_t roff = (size_t)(pt0 + p) * C_ + half * 128 + lane * 4;
                float4 v = *(const float4*)(pbase + roff);
                float a, bb;
                unpack2(a2[p][0], a, bb); v.x += a; v.y += bb;
                unpack2(a2[p][1], a, bb); v.z += a; v.w += bb;
                *(float4*)(obase + roff) = v;
            }
        }
    }
}

// ---------------------------------------------------------------------------
extern "C" void kernel_launch(void* const* d_in, const int* in_sizes, int n_in,
                              void* d_out, int out_size) {
    const float* pf = (const float*)d_in[0];   // point_features   (B,N,C)
    const float* cf = (const float*)d_in[1];   // centroid_features(B,NC,C)
    const float* Wp = (const float*)d_in[2];   // (C,C)
    const float* bp = (const float*)d_in[3];   // (C,)
    const float* Wc = (const float*)d_in[4];   // (C,C)
    const float* bc = (const float*)d_in[5];   // (C,)
    float* out = (float*)d_out;

    const int smem_bytes = 18944 * sizeof(float);   // 75.8 KB -> 3 blocks/SM

    static bool attr_set = false;
    if (!attr_set) {
        cudaFuncSetAttribute(attn_main_kernel,
                             cudaFuncAttributeMaxDynamicSharedMemorySize,
                             smem_bytes);
        attr_set = true;
    }

    prep_kernel<<<B_ * 16, 256>>>(cf, Wp, Wc, bp, bc);
    attn_main_kernel<<<B_ * (N_ / TP_), 256, smem_bytes>>>(pf, cf, out);
}